// round 5
// baseline (speedup 1.0000x reference)
#include <cuda_runtime.h>
#include <cstdint>

// TemporalEncoder: fc_in(64->128) + GRU(128->8) over (B=512, S=2048).
// Fused producer/consumer kernel, 128 blocks x 256 threads, block = 4 chains.
//   warps 0,1,2,4,5,6: projection (gates = W_comb @ a), 64-step windows,
//                      double-buffered in smem, gates packed as float4/slot.
//   warp 3:            idle (keeps SMSP 3 free for the consumer).
//   warp 7:            4-chain GRU scan, private SMSP, f32x2-packed dots.

#define BATCH 512
#define SEQ   2048
#define INSZ  64
#define HID   128
#define WSTEP 64                 // window steps
#define NWIN  (SEQ / WSTEP)      // 32
#define QROW  33                 // quads (float4) per gate row (32 slots + 1 pad)
#define STGF  (WSTEP * QROW * 4) // floats per stage = 8448
#define ROWP  68                 // padded A row stride (floats)

typedef unsigned long long ull;

__device__ float g_Wc[24 * 64];   // combined weights (r,z rows *0.5; n rows *1)
__device__ float g_bc[24];        // combined biases  (r,z incl bhh, *0.5; n raw)
__device__ float g_Whh_s[24 * 8]; // hidden weights, all rows *0.5
__device__ float g_bhn_s[8];      // 0.5*bhn

__device__ __forceinline__ ull pack2(float lo, float hi) {
    ull r; asm("mov.b64 %0, {%1,%2};" : "=l"(r) : "f"(lo), "f"(hi)); return r;
}
__device__ __forceinline__ ull fma2(ull a, ull b, ull c) {
    ull d; asm("fma.rn.f32x2 %0, %1, %2, %3;" : "=l"(d) : "l"(a), "l"(b), "l"(c)); return d;
}
__device__ __forceinline__ ull add2(ull a, ull b) {
    ull d; asm("add.rn.f32x2 %0, %1, %2;" : "=l"(d) : "l"(a), "l"(b)); return d;
}
__device__ __forceinline__ float2 unpack2(ull v) {
    float lo, hi; asm("mov.b64 {%0,%1}, %2;" : "=f"(lo), "=f"(hi) : "l"(v));
    return make_float2(lo, hi);
}
__device__ __forceinline__ float tanha(float x) {
    float y; asm("tanh.approx.f32 %0, %1;" : "=f"(y) : "f"(x)); return y;
}

// ---------------- prep ----------------
__global__ void __launch_bounds__(256) prep_kernel(
    const float* __restrict__ Win,  // [128,64]
    const float* __restrict__ bin,  // [128]
    const float* __restrict__ Wih,  // [24,128]
    const float* __restrict__ Whh,  // [24,8]
    const float* __restrict__ bih,  // [24]
    const float* __restrict__ bhh)  // [24]
{
    __shared__ float sWin[HID * INSZ];
    __shared__ float sWih[24 * HID];
    __shared__ float sbin[HID];
    int t = threadIdx.x;
    for (int i = t; i < HID * INSZ; i += 256) sWin[i] = Win[i];
    for (int i = t; i < 24 * HID; i += 256) sWih[i] = Wih[i];
    if (t < HID) sbin[t] = bin[t];
    __syncthreads();

    int e = blockIdx.x * 256 + t;     // 0..1535
    int g = e >> 6, i = e & 63;
    float s0 = 0.f, s1 = 0.f, s2 = 0.f, s3 = 0.f;
    for (int h = 0; h < HID; h += 4) {
        s0 = fmaf(sWih[g * HID + h],     sWin[h * INSZ + i],       s0);
        s1 = fmaf(sWih[g * HID + h + 1], sWin[(h + 1) * INSZ + i], s1);
        s2 = fmaf(sWih[g * HID + h + 2], sWin[(h + 2) * INSZ + i], s2);
        s3 = fmaf(sWih[g * HID + h + 3], sWin[(h + 3) * INSZ + i], s3);
    }
    g_Wc[e] = ((g < 16) ? 0.5f : 1.0f) * ((s0 + s1) + (s2 + s3));

    if (blockIdx.x == 0) {
        if (t < 24) {
            int gg = t;
            float s = 0.f;
            for (int h = 0; h < HID; h++) s = fmaf(sWih[gg * HID + h], sbin[h], s);
            s += bih[gg];
            if (gg < 16) { s += bhh[gg]; g_bc[gg] = 0.5f * s; }
            else         {               g_bc[gg] = s;        }
        }
        if (t < 24 * 8) g_Whh_s[t] = 0.5f * Whh[t];
        if (t < 8) g_bhn_s[t] = 0.5f * bhh[16 + t];
    }
}

// ---------------- fused proj + scan ----------------
__global__ void __launch_bounds__(256) fused_kernel(const float* __restrict__ A,
                                                    float* __restrict__ out) {
    extern __shared__ float sm[];
    float* sW = sm;                       // 1536
    float* sb = sW + 1536;                // 32
    float* sG = sb + 32;                  // 2 * STGF = 16896
    float* sA = sG + 2 * STGF;            // 7 * 32 * ROWP = 15232

    int tid = threadIdx.x;
    int wid = tid >> 5, lane = tid & 31;
    int chainBase = blockIdx.x * 4;

    for (int i = tid; i < 24 * 64; i += 256) sW[i] = g_Wc[i];
    if (tid < 24) sb[tid] = g_bc[tid];

    // ---- consumer (warp 7) setup: packed weights ----
    int j = lane & 7, c = lane >> 3, gb2 = lane & ~7;
    ull wr2[4], wz2[4], wn2[4], BQ2 = 0;
    float h = 0.f;
    if (wid == 7) {
#pragma unroll
        for (int m = 0; m < 4; m++) {
            wr2[m] = pack2(g_Whh_s[j * 8 + 2 * m],        g_Whh_s[j * 8 + 2 * m + 1]);
            wz2[m] = pack2(g_Whh_s[(8 + j) * 8 + 2 * m],  g_Whh_s[(8 + j) * 8 + 2 * m + 1]);
            wn2[m] = pack2(g_Whh_s[(16 + j) * 8 + 2 * m], g_Whh_s[(16 + j) * 8 + 2 * m + 1]);
        }
        BQ2 = pack2(g_bhn_s[j], 0.f);
    }
    float* sAw = sA + wid * 32 * ROWP;
    __syncthreads();

    // ---- producer: fill one window into a stage ----
    auto fill = [&](int w, int stage) {
        float* gst = sG + stage * STGF;
        int p = (wid < 3) ? wid : wid - 1;           // producer index 0..5
        for (int b = p; b < 8; b += 6) {             // 8 sub-batches over 6 warps
            int cb = b >> 1;
            int sHalf = (b & 1) * 32;
            const float4* ap = reinterpret_cast<const float4*>(
                A + ((size_t)(chainBase + cb) * SEQ + w * WSTEP + sHalf) * INSZ);
            __syncwarp();
#pragma unroll
            for (int rep = 0; rep < 16; rep++) {
                int f = rep * 32 + lane;
                float4 v = ap[f];
                int it = f >> 4, cc = f & 15;
                *reinterpret_cast<float4*>(sAw + it * ROWP + cc * 4) = v;
            }
            __syncwarp();
            ull a2[32];
            const float4* rp = reinterpret_cast<const float4*>(sAw + lane * ROWP);
#pragma unroll
            for (int cc = 0; cc < 16; cc++) {
                float4 v = rp[cc];
                a2[2 * cc]     = pack2(v.x, v.y);
                a2[2 * cc + 1] = pack2(v.z, v.w);
            }
            float res[24];
#pragma unroll
            for (int g = 0; g < 24; g++) {
                const ulonglong2* wp = reinterpret_cast<const ulonglong2*>(sW + g * 64);
                ull acc0 = pack2(sb[g], 0.f);
                ull acc1 = pack2(0.f, 0.f);
#pragma unroll
                for (int pp = 0; pp < 16; pp++) {
                    ulonglong2 wv = wp[pp];
                    acc0 = fma2(wv.x, a2[2 * pp], acc0);
                    acc1 = fma2(wv.y, a2[2 * pp + 1], acc1);
                }
                float2 q0 = unpack2(acc0), q1 = unpack2(acc1);
                res[g] = (q0.x + q0.y) + (q1.x + q1.y);
            }
            // packed gate store: one float4 per (step, j): (xr_j, xz_j, xn_j, 0)
            int stepW = sHalf + lane;
            float4* gout4 = reinterpret_cast<float4*>(gst) + stepW * QROW + cb;
#pragma unroll
            for (int jj = 0; jj < 8; jj++) {
                gout4[jj * 4] = make_float4(res[jj], res[8 + jj], res[16 + jj], 0.f);
            }
        }
    };

    if (wid < 7 && wid != 3) fill(0, 0);
    __syncthreads();

    const ull ZERO2 = pack2(0.f, 0.f);

    for (int w = 0; w < NWIN; w++) {
        int stage = w & 1;
        if (wid < 7 && wid != 3) {
            if (w + 1 < NWIN) fill(w + 1, stage ^ 1);
        } else if (wid == 7) {
            const float4* gq = reinterpret_cast<const float4*>(sG + stage * STGF)
                               + (4 * j + c);
            float4 cur = gq[0];
#pragma unroll 8
            for (int t = 0; t < WSTEP; t++) {
                float4 nxt = gq[((t + 1) & 63) * QROW];   // t=63: dummy reload of row 0

                float hv0 = __shfl_sync(0xffffffffu, h, gb2 + 0);
                float hv1 = __shfl_sync(0xffffffffu, h, gb2 + 1);
                float hv2 = __shfl_sync(0xffffffffu, h, gb2 + 2);
                float hv3 = __shfl_sync(0xffffffffu, h, gb2 + 3);
                float hv4 = __shfl_sync(0xffffffffu, h, gb2 + 4);
                float hv5 = __shfl_sync(0xffffffffu, h, gb2 + 5);
                float hv6 = __shfl_sync(0xffffffffu, h, gb2 + 6);
                float hv7 = __shfl_sync(0xffffffffu, h, gb2 + 7);
                ull H01 = pack2(hv0, hv1), H23 = pack2(hv2, hv3);
                ull H45 = pack2(hv4, hv5), H67 = pack2(hv6, hv7);

                ull xr2 = pack2(cur.x, 0.f);
                ull xz2 = pack2(cur.y, 0.f);

                ull ra0 = fma2(wr2[1], H23, fma2(wr2[0], H01, xr2));
                ull rb0 = fma2(wr2[3], H67, fma2(wr2[2], H45, ZERO2));
                ull za0 = fma2(wz2[1], H23, fma2(wz2[0], H01, xz2));
                ull zb0 = fma2(wz2[3], H67, fma2(wz2[2], H45, ZERO2));
                ull qa0 = fma2(wn2[1], H23, fma2(wn2[0], H01, BQ2));
                ull qb0 = fma2(wn2[3], H67, fma2(wn2[2], H45, ZERO2));

                float2 fr = unpack2(add2(ra0, rb0));
                float2 fz = unpack2(add2(za0, zb0));
                float2 fq = unpack2(add2(qa0, qb0));
                float tr = tanha(fr.x + fr.y);
                float tz = tanha(fz.x + fz.y);
                float qp = fq.x + fq.y;

                float narg = fmaf(tr, qp, cur.z + qp);
                float n = tanha(narg);
                float u0 = 0.5f * fmaf(tz, h, h);      // z*h
                float cc2 = fmaf(-0.5f, tz, 0.5f);     // 1-z
                h = fmaf(cc2, n, u0);

                cur = nxt;
            }
        }
        __syncthreads();
    }

    if (wid == 7) out[(chainBase + c) * 8 + j] = h;
}

extern "C" void kernel_launch(void* const* d_in, const int* in_sizes, int n_in,
                              void* d_out, int out_size) {
    const float* A   = (const float*)d_in[0];
    const float* Win = (const float*)d_in[1];
    const float* bin = (const float*)d_in[2];
    const float* Wih = (const float*)d_in[3];
    const float* Whh = (const float*)d_in[4];
    const float* bih = (const float*)d_in[5];
    const float* bhh = (const float*)d_in[6];

    static int configured = 0;
    size_t smem = (1536 + 32 + 2 * STGF + 7 * 32 * ROWP) * sizeof(float);  // ~135 KB
    if (!configured) {
        cudaFuncSetAttribute(fused_kernel, cudaFuncAttributeMaxDynamicSharedMemorySize,
                             (int)smem);
        configured = 1;
    }

    prep_kernel<<<6, 256>>>(Win, bin, Wih, Whh, bih, bhh);
    fused_kernel<<<BATCH / 4, 256, smem>>>(A, (float*)d_out);
}

// round 6
// speedup vs baseline: 1.1047x; 1.1047x over previous
#include <cuda_runtime.h>
#include <cstdint>

// TemporalEncoder: fc_in(64->128) + GRU(128->8) over (B=512, S=2048).
// Fused producer/consumer kernel, 128 blocks x 256 threads, block = 4 chains.
//   warps 0,1,2,4,5,6: projection (gates = W_comb @ a), 64-step windows,
//                      double-buffered in smem, gates packed (xr,xz,xn,_) float4.
//   warp 3:            idle (keeps SMSP 3 private for the consumer).
//   warp 7:            4-chain GRU scan, scalar FFMA dots, 1 LDS.128 per step.

#define BATCH 512
#define SEQ   2048
#define INSZ  64
#define HID   128
#define WSTEP 64                 // window steps
#define NWIN  (SEQ / WSTEP)      // 32
#define QROW  33                 // quads (float4) per step row (32 slots + 1 pad)
#define STGF  (WSTEP * QROW * 4) // floats per stage = 8448
#define ROWP  68                 // padded A row stride (floats)

typedef unsigned long long ull;

__device__ float g_Wc[24 * 64];   // combined weights (r,z rows *0.5; n rows *1)
__device__ float g_bc[24];        // combined biases  (r,z incl bhh, *0.5; n raw)
__device__ float g_Whh_s[24 * 8]; // hidden weights, all rows *0.5
__device__ float g_bhn_s[8];      // 0.5*bhn

__device__ __forceinline__ ull pack2(float lo, float hi) {
    ull r; asm("mov.b64 %0, {%1,%2};" : "=l"(r) : "f"(lo), "f"(hi)); return r;
}
__device__ __forceinline__ ull fma2(ull a, ull b, ull c) {
    ull d; asm("fma.rn.f32x2 %0, %1, %2, %3;" : "=l"(d) : "l"(a), "l"(b), "l"(c)); return d;
}
__device__ __forceinline__ float2 unpack2(ull v) {
    float lo, hi; asm("mov.b64 {%0,%1}, %2;" : "=f"(lo), "=f"(hi) : "l"(v));
    return make_float2(lo, hi);
}
__device__ __forceinline__ float tanha(float x) {
    float y; asm("tanh.approx.f32 %0, %1;" : "=f"(y) : "f"(x)); return y;
}

// ---------------- prep ----------------
__global__ void __launch_bounds__(256) prep_kernel(
    const float* __restrict__ Win,  // [128,64]
    const float* __restrict__ bin,  // [128]
    const float* __restrict__ Wih,  // [24,128]
    const float* __restrict__ Whh,  // [24,8]
    const float* __restrict__ bih,  // [24]
    const float* __restrict__ bhh)  // [24]
{
    __shared__ float sWin[HID * INSZ];
    __shared__ float sWih[24 * HID];
    __shared__ float sbin[HID];
    int t = threadIdx.x;
    for (int i = t; i < HID * INSZ; i += 256) sWin[i] = Win[i];
    for (int i = t; i < 24 * HID; i += 256) sWih[i] = Wih[i];
    if (t < HID) sbin[t] = bin[t];
    __syncthreads();

    int e = blockIdx.x * 256 + t;     // 0..1535
    int g = e >> 6, i = e & 63;
    float s0 = 0.f, s1 = 0.f, s2 = 0.f, s3 = 0.f;
    for (int h = 0; h < HID; h += 4) {
        s0 = fmaf(sWih[g * HID + h],     sWin[h * INSZ + i],       s0);
        s1 = fmaf(sWih[g * HID + h + 1], sWin[(h + 1) * INSZ + i], s1);
        s2 = fmaf(sWih[g * HID + h + 2], sWin[(h + 2) * INSZ + i], s2);
        s3 = fmaf(sWih[g * HID + h + 3], sWin[(h + 3) * INSZ + i], s3);
    }
    g_Wc[e] = ((g < 16) ? 0.5f : 1.0f) * ((s0 + s1) + (s2 + s3));

    if (blockIdx.x == 0) {
        if (t < 24) {
            int gg = t;
            float s = 0.f;
            for (int h = 0; h < HID; h++) s = fmaf(sWih[gg * HID + h], sbin[h], s);
            s += bih[gg];
            if (gg < 16) { s += bhh[gg]; g_bc[gg] = 0.5f * s; }
            else         {               g_bc[gg] = s;        }
        }
        if (t < 24 * 8) g_Whh_s[t] = 0.5f * Whh[t];
        if (t < 8) g_bhn_s[t] = 0.5f * bhh[16 + t];
    }
}

// ---------------- fused proj + scan ----------------
__global__ void __launch_bounds__(256) fused_kernel(const float* __restrict__ A,
                                                    float* __restrict__ out) {
    extern __shared__ float sm[];
    float* sW = sm;                       // 1536
    float* sb = sW + 1536;                // 32
    float* sG = sb + 32;                  // 2 * STGF = 16896
    float* sA = sG + 2 * STGF;            // 7 * 32 * ROWP = 15232

    int tid = threadIdx.x;
    int wid = tid >> 5, lane = tid & 31;
    int chainBase = blockIdx.x * 4;

    for (int i = tid; i < 24 * 64; i += 256) sW[i] = g_Wc[i];
    if (tid < 24) sb[tid] = g_bc[tid];

    // ---- consumer (warp 7) setup ----
    int j = lane & 7, c = lane >> 3, gb2 = lane & ~7;
    float wr[8], wz[8], wn[8], bq = 0.f, h = 0.f;
    if (wid == 7) {
#pragma unroll
        for (int k = 0; k < 8; k++) {
            wr[k] = g_Whh_s[j * 8 + k];
            wz[k] = g_Whh_s[(8 + j) * 8 + k];
            wn[k] = g_Whh_s[(16 + j) * 8 + k];
        }
        bq = g_bhn_s[j];
    }
    float* sAw = sA + wid * 32 * ROWP;
    __syncthreads();

    // ---- producer: fill one window into a stage ----
    auto fill = [&](int w, int stage) {
        float* gst = sG + stage * STGF;
        int p = (wid < 3) ? wid : wid - 1;           // producer index 0..5
        for (int b = p; b < 8; b += 6) {             // 8 sub-batches over 6 warps
            int cb = b >> 1;
            int sHalf = (b & 1) * 32;
            const float4* ap = reinterpret_cast<const float4*>(
                A + ((size_t)(chainBase + cb) * SEQ + w * WSTEP + sHalf) * INSZ);
            __syncwarp();
#pragma unroll
            for (int rep = 0; rep < 16; rep++) {
                int f = rep * 32 + lane;
                float4 v = ap[f];
                int it = f >> 4, cc = f & 15;
                *reinterpret_cast<float4*>(sAw + it * ROWP + cc * 4) = v;
            }
            __syncwarp();
            ull a2[32];
            const float4* rp = reinterpret_cast<const float4*>(sAw + lane * ROWP);
#pragma unroll
            for (int cc = 0; cc < 16; cc++) {
                float4 v = rp[cc];
                a2[2 * cc]     = pack2(v.x, v.y);
                a2[2 * cc + 1] = pack2(v.z, v.w);
            }
            float res[24];
#pragma unroll
            for (int g = 0; g < 24; g++) {
                const ulonglong2* wp = reinterpret_cast<const ulonglong2*>(sW + g * 64);
                ull acc0 = pack2(sb[g], 0.f);
                ull acc1 = pack2(0.f, 0.f);
#pragma unroll
                for (int pp = 0; pp < 16; pp++) {
                    ulonglong2 wv = wp[pp];
                    acc0 = fma2(wv.x, a2[2 * pp], acc0);
                    acc1 = fma2(wv.y, a2[2 * pp + 1], acc1);
                }
                float2 q0 = unpack2(acc0), q1 = unpack2(acc1);
                res[g] = (q0.x + q0.y) + (q1.x + q1.y);
            }
            // packed gate store: one float4 per (step, j): (xr_j, xz_j, xn_j, 0)
            int stepW = sHalf + lane;
            float4* gout4 = reinterpret_cast<float4*>(gst) + stepW * QROW + cb;
#pragma unroll
            for (int jj = 0; jj < 8; jj++) {
                gout4[jj * 4] = make_float4(res[jj], res[8 + jj], res[16 + jj], 0.f);
            }
        }
    };

    if (wid < 7 && wid != 3) fill(0, 0);
    __syncthreads();

    for (int w = 0; w < NWIN; w++) {
        int stage = w & 1;
        if (wid < 7 && wid != 3) {
            if (w + 1 < NWIN) fill(w + 1, stage ^ 1);
        } else if (wid == 7) {
            const float4* gq = reinterpret_cast<const float4*>(sG + stage * STGF)
                               + (4 * j + c);
            float4 cur = gq[0];
#pragma unroll 8
            for (int t = 0; t < WSTEP; t++) {
                int t2 = (t + 1 < WSTEP) ? t + 1 : t;
                float4 nxt = gq[t2 * QROW];

                float hv[8];
#pragma unroll
                for (int k = 0; k < 8; k++) hv[k] = __shfl_sync(0xffffffffu, h, gb2 + k);

                float ra = cur.x, za = cur.y, qa = bq;
                float rb = wr[4] * hv[4], zb = wz[4] * hv[4], qb = wn[4] * hv[4];
#pragma unroll
                for (int k = 0; k < 4; k++) {
                    ra = fmaf(wr[k], hv[k], ra);
                    za = fmaf(wz[k], hv[k], za);
                    qa = fmaf(wn[k], hv[k], qa);
                }
#pragma unroll
                for (int k = 5; k < 8; k++) {
                    rb = fmaf(wr[k], hv[k], rb);
                    zb = fmaf(wz[k], hv[k], zb);
                    qb = fmaf(wn[k], hv[k], qb);
                }
                float tr = tanha(ra + rb);
                float tz = tanha(za + zb);
                float qp = qa + qb;                  // q' = 0.5*(Whn h + bhn)

                float narg = fmaf(tr, qp, cur.z + qp);
                float n = tanha(narg);
                float u0 = 0.5f * fmaf(tz, h, h);    // z*h
                float cc2 = fmaf(-0.5f, tz, 0.5f);   // 1-z
                h = fmaf(cc2, n, u0);

                cur = nxt;
            }
        }
        __syncthreads();
    }

    if (wid == 7) out[(chainBase + c) * 8 + j] = h;
}

extern "C" void kernel_launch(void* const* d_in, const int* in_sizes, int n_in,
                              void* d_out, int out_size) {
    const float* A   = (const float*)d_in[0];
    const float* Win = (const float*)d_in[1];
    const float* bin = (const float*)d_in[2];
    const float* Wih = (const float*)d_in[3];
    const float* Whh = (const float*)d_in[4];
    const float* bih = (const float*)d_in[5];
    const float* bhh = (const float*)d_in[6];

    static int configured = 0;
    size_t smem = (1536 + 32 + 2 * STGF + 7 * 32 * ROWP) * sizeof(float);  // ~132 KB
    if (!configured) {
        cudaFuncSetAttribute(fused_kernel, cudaFuncAttributeMaxDynamicSharedMemorySize,
                             (int)smem);
        configured = 1;
    }

    prep_kernel<<<6, 256>>>(Win, bin, Wih, Whh, bih, bhh);
    fused_kernel<<<BATCH / 4, 256, smem>>>(A, (float*)d_out);
}